// round 8
// baseline (speedup 1.0000x reference)
#include <cuda_runtime.h>
#include <cstdint>

#define NB   32
#define H    1024
#define W    1024
#define BH   73
#define BW   73
#define BS   14                  // block stride = 16 - 3 + 1
#define NROWS (NB*BH)            // 2336 flag rows
#define TOTAL (NB*BH*BW)         // 170528
#define GRP2 37                  // ceil(73/2) strip-pairs per image

__device__ unsigned g_bits[NROWS * 3];   // 73-bit mask per row (slow path only)
__device__ int g_csum[NROWS];
__device__ int g_coff[NROWS];
__device__ int g_count;

// ---------------------------------------------------------------------------
// Kernel 1: fused pad + 16x16/stride14 max-pool + threshold.
// 256 threads per CTA, 2 strips per CTA (grid 32*37=1184 -> 303k threads).
// Each thread issues 2 independent float4 loads (front-batched, MLP_p1=2)
// into smem. Threads 0-127 evaluate strip 0's 73 windows over the probe row
// (by*14), threads 128-255 strip 1, via per-warp ballots. A window is
// decided-active unless all 16 probe samples <= 0.5 (p = 2^-16); undecided
// strips (~3 per launch) take a warp-local full 16-row slow path.
// ---------------------------------------------------------------------------
__global__ __launch_bounds__(256) void pool_kernel(const float* __restrict__ mask) {
    const int cta = blockIdx.x;           // n*GRP2 + grp
    const int n   = cta / GRP2;
    const int by0 = (cta % GRP2) * 2;
    const int t    = threadIdx.x;
    const int warp = t >> 5, lane = t & 31;

    __shared__ float rows[2][W];          // 8KB
    __shared__ unsigned sball[8];

    const float4* base4 = (const float4*)(mask + (size_t)n * H * W);
    const int by1ok = (by0 + 1) < BH;     // by0 always < BH

    // ---- front-batched loads: 2 probe rows, 1 float4 chunk per thread each
    const float4* s0 = base4 + (size_t)(by0 * BS) * (W / 4);
    const float4* s1 = base4 + (size_t)((by0 + by1ok) * BS) * (W / 4);
    float4 a = s0[t];
    float4 b = s1[t];                     // duplicate of s0 when !by1ok (harmless)
    ((float4*)rows[0])[t] = a;
    ((float4*)rows[1])[t] = b;
    __syncthreads();

    // ---- evaluate: side = strip index, wi = window index within strip ----
    const int side = t >> 7;
    const int wi   = t & 127;
    const float* cm = rows[side];
    int flag = 0;
    if (wi < BW && (side == 0 || by1ok)) {
        float mx = 0.f;
        int c0 = wi * BS - 1;
#pragma unroll
        for (int k = 0; k < 16; k++) {
            int c = c0 + k;
            if (c >= 0 && c < W) mx = fmaxf(mx, cm[c]);
        }
        flag = (mx > 0.5f) ? 1 : 0;
    }
    unsigned bal = __ballot_sync(0xffffffffu, flag);
    if (lane == 0) sball[warp] = bal;
    __syncthreads();

    // ---- decide per strip: warp 0 -> strip 0, warp 4 -> strip 1 ----
    if ((warp & 3) != 0) return;
    const int s = warp >> 2;              // 0 or 1
    if (s == 1 && !by1ok) return;
    const int by  = by0 + s;
    const int row = n * BH + by;

    unsigned b0 = sball[4 * s + 0];
    unsigned b1 = sball[4 * s + 1];
    unsigned b2 = sball[4 * s + 2];       // only wi 64..72 can be set
    int cnt = __popc(b0) + __popc(b1) + __popc(b2);

    if (cnt == BW) {                      // fast path: every window active
        if (lane == 0) g_csum[row] = BW;
        return;
    }

    // ---- warp-local slow path: full 16-row colmax, then re-evaluate ----
    float* wm = rows[s];                  // safe: all probe reads of this row done
    const int row0 = by * BS - 1;         // may be -1 (zero pad); row0+15 <= 1022
#pragma unroll
    for (int ch = 0; ch < 8; ch++) {      // 8 chunks x 32 lanes x float4 = 1024 cols
        float4 m = make_float4(0.f, 0.f, 0.f, 0.f);
        for (int r = 0; r < 16; r++) {
            int real = row0 + r;
            if (real < 0) continue;
            float4 u = base4[(size_t)real * (W / 4) + ch * 32 + lane];
            m.x = fmaxf(m.x, u.x); m.y = fmaxf(m.y, u.y);
            m.z = fmaxf(m.z, u.z); m.w = fmaxf(m.w, u.w);
        }
        ((float4*)wm)[ch * 32 + lane] = m;
    }
    __syncwarp();

    unsigned bits[3];
#pragma unroll
    for (int i = 0; i < 3; i++) {
        int w2 = i * 32 + lane;
        int fl = 0;
        if (w2 < BW) {
            float mx = 0.f;
            int c0 = w2 * BS - 1;
#pragma unroll
            for (int k = 0; k < 16; k++) {
                int c = c0 + k;
                if (c >= 0 && c < W) mx = fmaxf(mx, wm[c]);
            }
            fl = (mx > 0.5f) ? 1 : 0;
        }
        bits[i] = __ballot_sync(0xffffffffu, fl);
    }
    if (lane == 0) {
        g_bits[row * 3 + 0] = bits[0];
        g_bits[row * 3 + 1] = bits[1];
        g_bits[row * 3 + 2] = bits[2];
        g_csum[row] = __popc(bits[0]) + __popc(bits[1]) + __popc(bits[2]);
    }
}

// ---------------------------------------------------------------------------
// Kernel 2: parallel exclusive scan of 2336 row sums (1 CTA, 256 threads).
// ---------------------------------------------------------------------------
#define PER 10   // 256*10 = 2560 >= 2336

__global__ __launch_bounds__(256) void scan_kernel(float* __restrict__ out,
                                                   int count_idx) {
    const int t = threadIdx.x;
    const int lane = t & 31, w = t >> 5;
    __shared__ int wtot[8];
    __shared__ int woff[8];

    int local[PER];
    int s = 0;
    int base = t * PER;
#pragma unroll
    for (int i = 0; i < PER; i++) {
        int g = base + i;
        local[i] = (g < NROWS) ? g_csum[g] : 0;
        s += local[i];
    }

    int x = s;                            // warp inclusive scan
#pragma unroll
    for (int off = 1; off < 32; off <<= 1) {
        int y = __shfl_up_sync(0xffffffffu, x, off);
        if (lane >= off) x += y;
    }
    if (lane == 31) wtot[w] = x;
    __syncthreads();
    if (t == 0) {
        int acc = 0;
        for (int i = 0; i < 8; i++) { woff[i] = acc; acc += wtot[i]; }
        g_count = acc;
        if (count_idx >= 0) out[count_idx] = (float)acc;
    }
    __syncthreads();

    int excl = woff[w] + x - s;
#pragma unroll
    for (int i = 0; i < PER; i++) {
        int g = base + i;
        if (g < NROWS) g_coff[g] = excl;
        excl += local[i];
    }
}

// ---------------------------------------------------------------------------
// Kernel 3: scatter. One CTA (96 thr) per row. Fast rows (csum==73) write
// their 73 active triples directly. Slow rows use the bitmask + popc prefix;
// inactive elements write the fill triple at count + inactive_rank (inactive
// ranks are globally contiguous), so no tail-fill pass is needed.
// ---------------------------------------------------------------------------
__global__ __launch_bounds__(96) void scatter_kernel(float* __restrict__ out) {
    const int row = blockIdx.x;          // n*BH + by
    const int t = threadIdx.x;
    if (t >= BW) return;

    const int cnt = g_csum[row];
    const int off = g_coff[row];
    const int i0 = row / BH;
    const int i1 = row - i0 * BH;

    if (cnt == BW) {                     // fast path: all 73 active
        int pos = off + t;
        out[3 * pos + 0] = (float)i0;
        out[3 * pos + 1] = (float)i1;
        out[3 * pos + 2] = (float)t;
        return;
    }

    unsigned w0 = g_bits[row * 3 + 0];
    unsigned w1 = g_bits[row * 3 + 1];
    unsigned w2 = g_bits[row * 3 + 2];
    unsigned lmask = (1u << (t & 31)) - 1u;

    int below, f;
    if (t < 32)      { below = __popc(w0 & lmask);                           f = (w0 >> t) & 1; }
    else if (t < 64) { below = __popc(w0) + __popc(w1 & lmask);              f = (w1 >> (t - 32)) & 1; }
    else             { below = __popc(w0) + __popc(w1) + __popc(w2 & lmask); f = (w2 >> (t - 64)) & 1; }

    if (f) {
        int pos = off + below;
        out[3 * pos + 0] = (float)i0;
        out[3 * pos + 1] = (float)i1;
        out[3 * pos + 2] = (float)t;
    } else {
        int g = row * BW + t;
        int pos = g_count + (g - (off + below));   // contiguous inactive ranks
        out[3 * pos + 0] = (float)NB;
        out[3 * pos + 1] = (float)BH;
        out[3 * pos + 2] = (float)BW;
    }
}

extern "C" void kernel_launch(void* const* d_in, const int* in_sizes, int n_in,
                              void* d_out, int out_size) {
    const float* mask = (const float*)d_in[0];
    float* out = (float*)d_out;

    int count_idx = (out_size > 3 * TOTAL) ? (out_size - 1) : -1;

    pool_kernel<<<NB * GRP2, 256>>>(mask);
    scan_kernel<<<1, 256>>>(out, count_idx);
    scatter_kernel<<<NROWS, 96>>>(out);
}

// round 10
// speedup vs baseline: 1.4005x; 1.4005x over previous
#include <cuda_runtime.h>
#include <cstdint>

#define NB   32
#define H    1024
#define W    1024
#define BH   73
#define BW   73
#define BS   14                  // block stride = 16 - 3 + 1
#define NROWS (NB*BH)            // 2336 flag rows
#define TOTAL (NB*BH*BW)         // 170528

__device__ unsigned g_bits[NROWS * 3];   // 73-bit mask per row (slow path only)
__device__ int g_csum[NROWS];
__device__ int g_coff[NROWS];
__device__ int g_count;

// ---------------------------------------------------------------------------
// Kernel 1: fused pad + 16x16/stride14 max-pool + threshold.
// R5 shape: one 256-thread CTA per (n, by) strip, ONE float4 load per thread
// from the probe row (by*14). Eval via ballot bitmap: bit j = any of chunk
// j's 4 floats > 0.5 (8 words in smem). Window wi is certified active if any
// FULLY-CONTAINED chunk (3-4 of them) is hot -> 64-bit shift+mask, no float
// smem, no strided LDS. Undecided windows (p = 2^-12, ~40 strips/launch)
// trigger a CTA-wide 16-row slow path (thread t = column chunk t).
// ---------------------------------------------------------------------------
__global__ __launch_bounds__(256) void pool_kernel(const float* __restrict__ mask) {
    const int cta = blockIdx.x;          // n*BH + by
    const int n  = cta / BH;
    const int by = cta % BH;
    const int t  = threadIdx.x;
    const int warp = t >> 5, lane = t & 31;

    __shared__ __align__(16) float cm[W];   // slow path only; 16B for STS.128
    __shared__ unsigned sball[9];            // 8 ballot words + zero pad

    const float4* base4 = (const float4*)(mask + (size_t)n * H * W);

    // ---- probe: one float4 per thread from row by*14 ----
    float4 v = base4[(size_t)(by * BS) * (W / 4) + t];
    int hot = (v.x > 0.5f) | (v.y > 0.5f) | (v.z > 0.5f) | (v.w > 0.5f);
    unsigned bal = __ballot_sync(0xffffffffu, hot);
    if (lane == 0) sball[warp] = bal;
    if (t == 0) sball[8] = 0u;
    __syncthreads();

    // ---- window eval from chunk bits ----
    int flag = 0;
    if (t < BW) {
        int lo = t * BS - 1; if (lo < 0) lo = 0;
        int hi = t * BS + 14;            // <= 1022, always in range
        int jlo = (lo + 3) >> 2;         // first fully-contained 4-chunk
        int jhi = (hi - 3) >> 2;         // last fully-contained 4-chunk
        int jw = jlo >> 5, jb = jlo & 31;
        unsigned long long w =
            ((unsigned long long)sball[jw + 1] << 32) | (unsigned long long)sball[jw];
        unsigned m = (1u << (jhi - jlo + 1)) - 1u;
        flag = ((w >> jb) & (unsigned long long)m) != 0ull;
    }
    int und = __syncthreads_count(t < BW && !flag);

    if (und == 0) {                      // fast path: every window active
        if (t == 0) g_csum[cta] = BW;
        return;
    }

    // ---- slow path (rare): thread t = column chunk t over all 16 rows ----
    const int row0 = by * BS - 1;        // may be -1 (zero pad); row0+15 <= 1022
    {
        const float4* colp = base4 + t;  // stride W/4 between rows
        float4 m4 = make_float4(0.f, 0.f, 0.f, 0.f);
#pragma unroll 4
        for (int r = 0; r < 16; r++) {
            int real = row0 + r;
            if (real >= 0) {
                float4 u = colp[(size_t)real * (W / 4)];
                m4.x = fmaxf(m4.x, u.x); m4.y = fmaxf(m4.y, u.y);
                m4.z = fmaxf(m4.z, u.z); m4.w = fmaxf(m4.w, u.w);
            }
        }
        ((float4*)cm)[t] = m4;
    }
    __syncthreads();

    flag = 0;
    if (t < BW) {
        float mx = 0.f;
        int c0 = t * BS - 1;
#pragma unroll
        for (int k = 0; k < 16; k++) {
            int c = c0 + k;
            if (c >= 0) mx = fmaxf(mx, cm[c]);   // c <= 1022 guaranteed
        }
        flag = (mx > 0.5f) ? 1 : 0;
    }
    unsigned wb = __ballot_sync(0xffffffffu, flag);  // t<73 guard zeroes rest
    if (lane == 0 && warp < 3) g_bits[cta * 3 + warp] = wb;
    int cnt = __syncthreads_count(flag);
    if (t == 0) g_csum[cta] = cnt;
}

// ---------------------------------------------------------------------------
// Kernel 2: parallel exclusive scan of 2336 row sums (1 CTA, 256 threads).
// ---------------------------------------------------------------------------
#define PER 10   // 256*10 = 2560 >= 2336

__global__ __launch_bounds__(256) void scan_kernel(float* __restrict__ out,
                                                   int count_idx) {
    const int t = threadIdx.x;
    const int lane = t & 31, w = t >> 5;
    __shared__ int wtot[8];
    __shared__ int woff[8];

    int local[PER];
    int s = 0;
    int base = t * PER;
#pragma unroll
    for (int i = 0; i < PER; i++) {
        int g = base + i;
        local[i] = (g < NROWS) ? g_csum[g] : 0;
        s += local[i];
    }

    int x = s;                            // warp inclusive scan
#pragma unroll
    for (int off = 1; off < 32; off <<= 1) {
        int y = __shfl_up_sync(0xffffffffu, x, off);
        if (lane >= off) x += y;
    }
    if (lane == 31) wtot[w] = x;
    __syncthreads();
    if (t == 0) {
        int acc = 0;
        for (int i = 0; i < 8; i++) { woff[i] = acc; acc += wtot[i]; }
        g_count = acc;
        if (count_idx >= 0) out[count_idx] = (float)acc;
    }
    __syncthreads();

    int excl = woff[w] + x - s;
#pragma unroll
    for (int i = 0; i < PER; i++) {
        int g = base + i;
        if (g < NROWS) g_coff[g] = excl;
        excl += local[i];
    }
}

// ---------------------------------------------------------------------------
// Kernel 3: scatter. One CTA (96 thr) per row. Fast rows (csum==73) write
// their 73 active triples directly. Slow rows use the bitmask + popc prefix;
// inactive elements write the fill triple at count + inactive_rank (inactive
// ranks are globally contiguous), so no tail-fill pass is needed.
// ---------------------------------------------------------------------------
__global__ __launch_bounds__(96) void scatter_kernel(float* __restrict__ out) {
    const int row = blockIdx.x;          // n*BH + by
    const int t = threadIdx.x;
    if (t >= BW) return;

    const int cnt = g_csum[row];
    const int off = g_coff[row];
    const int i0 = row / BH;
    const int i1 = row - i0 * BH;

    if (cnt == BW) {                     // fast path: all 73 active
        int pos = off + t;
        out[3 * pos + 0] = (float)i0;
        out[3 * pos + 1] = (float)i1;
        out[3 * pos + 2] = (float)t;
        return;
    }

    unsigned w0 = g_bits[row * 3 + 0];
    unsigned w1 = g_bits[row * 3 + 1];
    unsigned w2 = g_bits[row * 3 + 2];
    unsigned lmask = (1u << (t & 31)) - 1u;

    int below, f;
    if (t < 32)      { below = __popc(w0 & lmask);                           f = (w0 >> t) & 1; }
    else if (t < 64) { below = __popc(w0) + __popc(w1 & lmask);              f = (w1 >> (t - 32)) & 1; }
    else             { below = __popc(w0) + __popc(w1) + __popc(w2 & lmask); f = (w2 >> (t - 64)) & 1; }

    if (f) {
        int pos = off + below;
        out[3 * pos + 0] = (float)i0;
        out[3 * pos + 1] = (float)i1;
        out[3 * pos + 2] = (float)t;
    } else {
        int g = row * BW + t;
        int pos = g_count + (g - (off + below));   // contiguous inactive ranks
        out[3 * pos + 0] = (float)NB;
        out[3 * pos + 1] = (float)BH;
        out[3 * pos + 2] = (float)BW;
    }
}

extern "C" void kernel_launch(void* const* d_in, const int* in_sizes, int n_in,
                              void* d_out, int out_size) {
    const float* mask = (const float*)d_in[0];
    float* out = (float*)d_out;

    int count_idx = (out_size > 3 * TOTAL) ? (out_size - 1) : -1;

    pool_kernel<<<NROWS, 256>>>(mask);
    scan_kernel<<<1, 256>>>(out, count_idx);
    scatter_kernel<<<NROWS, 96>>>(out);
}

// round 11
// speedup vs baseline: 1.7173x; 1.2262x over previous
#include <cuda_runtime.h>
#include <cstdint>

#define NB   32
#define H    1024
#define W    1024
#define BH   73
#define BW   73
#define BS   14                  // block stride = 16 - 3 + 1
#define NROWS (NB*BH)            // 2336 flag rows
#define TOTAL (NB*BH*BW)         // 170528

__device__ unsigned long long g_acc;     // low32: running count, high32: done ctr
__device__ unsigned g_bits[NROWS * 3];   // 73-bit mask per row (slow path only)
__device__ int g_csum[NROWS];
__device__ int g_coff[NROWS];            // fixup scratch

// ---------------------------------------------------------------------------
// Rare-path fixup (p ~ 2^-244): some window was inactive, so the speculative
// layout (prefix = 73*row) is wrong. Rebuild the whole output from
// g_csum/g_bits with this single CTA. Perf-irrelevant; correctness only.
// ---------------------------------------------------------------------------
__device__ __noinline__ void fixup(float* __restrict__ out, int total) {
    const int t = threadIdx.x;
    if (t == 0) {
        int acc = 0;
        for (int i = 0; i < NROWS; i++) { g_coff[i] = acc; acc += g_csum[i]; }
    }
    __syncthreads();
    for (int g = t; g < TOTAL; g += 256) {
        int row = g / BW, col = g - (g / BW) * BW;
        int cnt = g_csum[row], off = g_coff[row];
        int below, f;
        if (cnt == BW) { below = col; f = 1; }
        else {
            unsigned w0 = g_bits[row * 3 + 0];
            unsigned w1 = g_bits[row * 3 + 1];
            unsigned w2 = g_bits[row * 3 + 2];
            unsigned lm = (1u << (col & 31)) - 1u;
            if (col < 32)      { below = __popc(w0 & lm);                           f = (w0 >> col) & 1; }
            else if (col < 64) { below = __popc(w0) + __popc(w1 & lm);              f = (w1 >> (col - 32)) & 1; }
            else               { below = __popc(w0) + __popc(w1) + __popc(w2 & lm); f = (w2 >> (col - 64)) & 1; }
        }
        if (f) {
            int pos = off + below;
            int i0 = row / BH;
            out[3 * pos + 0] = (float)i0;
            out[3 * pos + 1] = (float)(row - i0 * BH);
            out[3 * pos + 2] = (float)col;
        } else {
            int pos = total + (g - (off + below));
            out[3 * pos + 0] = (float)NB;
            out[3 * pos + 1] = (float)BH;
            out[3 * pos + 2] = (float)BW;
        }
    }
}

// ---------------------------------------------------------------------------
// Single fused kernel: pad + 16x16/stride14 max-pool + threshold + compact.
// One 256-thread CTA per (n, by) strip.
//  1) Speculative output: write this row's 73 triples at prefix 73*cta
//     (valid iff every window everywhere is active; p(deviation) ~ 2^-244).
//     Issued BEFORE the probe load -> hidden in the load shadow.
//  2) Probe: one float4/thread from row by*14; ballot bitmap of hot 4-chunks;
//     window certified active if any fully-contained chunk is hot.
//  3) Undecided windows (p = 2^-12) -> CTA-wide 16-row slow path.
//  4) Packed 64-bit atomic accumulates (count, done). Last CTA writes the
//     count slot, runs fixup if count != TOTAL, resets the accumulator.
// ---------------------------------------------------------------------------
__global__ __launch_bounds__(256) void fused_kernel(const float* __restrict__ mask,
                                                    float* __restrict__ out,
                                                    int count_idx) {
    const int cta = blockIdx.x;          // n*BH + by
    const int n  = cta / BH;
    const int by = cta - n * BH;
    const int t  = threadIdx.x;
    const int warp = t >> 5, lane = t & 31;

    __shared__ __align__(16) float cm[W];   // slow path only
    __shared__ unsigned sball[9];            // 8 ballot words + zero pad
    __shared__ int s_last;
    __shared__ unsigned s_tot;

    // ---- 1) speculative output triples (no data dependency) ----
    if (t < 3 * BW) {
        int c = t - (t / 3) * 3;
        int p = t / 3;
        float val = (c == 0) ? (float)n : (c == 1) ? (float)by : (float)p;
        out[(size_t)cta * (3 * BW) + t] = val;
    }

    const float4* base4 = (const float4*)(mask + (size_t)n * H * W);

    // ---- 2) probe: one float4 per thread from row by*14 ----
    float4 v = base4[(size_t)(by * BS) * (W / 4) + t];
    int hot = (v.x > 0.5f) | (v.y > 0.5f) | (v.z > 0.5f) | (v.w > 0.5f);
    unsigned bal = __ballot_sync(0xffffffffu, hot);
    if (lane == 0) sball[warp] = bal;
    if (t == 0) sball[8] = 0u;
    __syncthreads();

    int flag = 0;
    if (t < BW) {
        int lo = t * BS - 1; if (lo < 0) lo = 0;
        int hi = t * BS + 14;            // <= 1022, always in range
        int jlo = (lo + 3) >> 2;         // first fully-contained 4-chunk
        int jhi = (hi - 3) >> 2;         // last fully-contained 4-chunk
        int jw = jlo >> 5, jb = jlo & 31;
        unsigned long long w =
            ((unsigned long long)sball[jw + 1] << 32) | (unsigned long long)sball[jw];
        unsigned m = (1u << (jhi - jlo + 1)) - 1u;
        flag = ((w >> jb) & (unsigned long long)m) != 0ull;
    }
    int und = __syncthreads_count(t < BW && !flag);

    int csum;
    if (und == 0) {
        csum = BW;                        // fast path: every window active
    } else {
        // ---- 3) slow path (rare): thread t = column chunk t over 16 rows ----
        const int row0 = by * BS - 1;     // may be -1 (zero pad); row0+15 <= 1022
        {
            const float4* colp = base4 + t;
            float4 m4 = make_float4(0.f, 0.f, 0.f, 0.f);
#pragma unroll 4
            for (int r = 0; r < 16; r++) {
                int real = row0 + r;
                if (real >= 0) {
                    float4 u = colp[(size_t)real * (W / 4)];
                    m4.x = fmaxf(m4.x, u.x); m4.y = fmaxf(m4.y, u.y);
                    m4.z = fmaxf(m4.z, u.z); m4.w = fmaxf(m4.w, u.w);
                }
            }
            ((float4*)cm)[t] = m4;
        }
        __syncthreads();

        int fl = 0;
        if (t < BW) {
            float mx = 0.f;
            int c0 = t * BS - 1;
#pragma unroll
            for (int k = 0; k < 16; k++) {
                int c = c0 + k;
                if (c >= 0) mx = fmaxf(mx, cm[c]);   // c <= 1022 guaranteed
            }
            fl = (mx > 0.5f) ? 1 : 0;
        }
        unsigned wb = __ballot_sync(0xffffffffu, fl);  // t<73 guard zeroes rest
        if (lane == 0 && warp < 3) g_bits[cta * 3 + warp] = wb;
        csum = __syncthreads_count(fl);
    }

    // ---- 4) packed atomic: accumulate count + completion ----
    if (t == 0) {
        g_csum[cta] = csum;
        __threadfence();                  // csum/bits visible before the arrive
        unsigned long long old =
            atomicAdd(&g_acc, (unsigned long long)(unsigned)csum | (1ull << 32));
        if ((unsigned)(old >> 32) == NROWS - 1) {
            s_last = 1;
            s_tot  = (unsigned)(old & 0xffffffffu) + (unsigned)csum;
        } else {
            s_last = 0;
        }
    }
    __syncthreads();
    if (!s_last) return;

    // last CTA: count slot, rare fixup, reset for next graph replay
    if (t == 0 && count_idx >= 0) out[count_idx] = (float)s_tot;
    if (s_tot != TOTAL) {
        __threadfence();
        fixup(out, (int)s_tot);
    }
    __syncthreads();
    if (t == 0) g_acc = 0ull;
}

extern "C" void kernel_launch(void* const* d_in, const int* in_sizes, int n_in,
                              void* d_out, int out_size) {
    const float* mask = (const float*)d_in[0];
    float* out = (float*)d_out;

    int count_idx = (out_size > 3 * TOTAL) ? (out_size - 1) : -1;

    fused_kernel<<<NROWS, 256>>>(mask, out, count_idx);
}